// round 5
// baseline (speedup 1.0000x reference)
#include <cuda_runtime.h>
#include <cuda_fp16.h>
#include <math.h>

#define BATCH   512
#define T_STEPS 512
#define CHAN    32
#define CIN     33
#define HID     128
#define GATES   512   // 4*H
#define EPSF    1e-12f

// ---------------------------------------------------------------------------
// Device scratch (static; allocations are forbidden)
// ---------------------------------------------------------------------------
__device__ float  g_std_arr[T_STEPS];                   // minibatch-std scalar per t
__device__ float  g_inv_arr[4];                         // 1/sigma: ih, hh, fc
__device__ float  g_wt[CIN * GATES];                    // Wih^T scaled: [33][512]
__device__ float  g_bias[GATES];                        // b_ih + b_hh
__device__ __half g_whh_h[GATES * HID];                 // Whh scaled, fp16
__device__ float  g_gates[(size_t)BATCH * T_STEPS * GATES]; // 536 MB gates_x

// ---------------------------------------------------------------------------
// Kernel A: minibatch std feature. grid=T, block=256 (8 b-seg x 32 chan)
// ---------------------------------------------------------------------------
__global__ void std_kernel(const float* __restrict__ x)
{
    int t   = blockIdx.x;
    int tid = threadIdx.x;
    int c   = tid & 31;
    int seg = tid >> 5;

    float s = 0.f, ss = 0.f;
    for (int b = seg; b < BATCH; b += 8) {
        float v = x[((size_t)b * T_STEPS + t) * CHAN + c];
        s  += v;
        ss += v * v;
    }
    __shared__ float sm1[256], sm2[256];
    sm1[tid] = s; sm2[tid] = ss;
    __syncthreads();
    if (seg == 0) {
        for (int k = 1; k < 8; k++) { s += sm1[k * 32 + c]; ss += sm2[k * 32 + c]; }
        float mean = s * (1.f / 512.f);
        float var  = (ss - 512.f * mean * mean) * (1.f / 511.f);
        float sd   = sqrtf(fmaxf(var, 0.f));
        #pragma unroll
        for (int off = 16; off; off >>= 1)
            sd += __shfl_xor_sync(0xffffffffu, sd, off);
        if (c == 0) g_std_arr[t] = sd * (1.f / 32.f);
    }
}

// ---------------------------------------------------------------------------
// Kernel B: spectral norms (one power iteration, matching reference exactly)
// then scale+transpose Wih, combine bias, quantize Whh to fp16.
// single block, 512 threads
// ---------------------------------------------------------------------------
__global__ void prep_kernel(const float* __restrict__ wih, const float* __restrict__ uih,
                            const float* __restrict__ whh, const float* __restrict__ uhh,
                            const float* __restrict__ bih, const float* __restrict__ bhh,
                            const float* __restrict__ wfc, const float* __restrict__ ufc)
{
    __shared__ float tv[HID];
    __shared__ float red[512];
    __shared__ float nrm;
    __shared__ float inv_s[4];
    int tid = threadIdx.x;

    // ---- ih: W [512,33] ----
    if (tid < CIN) {
        float s = 0.f;
        for (int g = 0; g < GATES; g++) s += wih[g * CIN + tid] * uih[g];
        tv[tid] = s;
    }
    __syncthreads();
    if (tid == 0) {
        float n = 0.f;
        for (int c = 0; c < CIN; c++) n += tv[c] * tv[c];
        nrm = sqrtf(n) + EPSF;
    }
    __syncthreads();
    {
        float a = 0.f;
        for (int c = 0; c < CIN; c++) a += wih[tid * CIN + c] * tv[c];
        a /= nrm;
        red[tid] = a * a;
    }
    __syncthreads();
    for (int off = 256; off; off >>= 1) {
        if (tid < off) red[tid] += red[tid + off];
        __syncthreads();
    }
    if (tid == 0) {
        float ssum = red[0];                      // ||W v||^2
        float v = (sqrtf(ssum) + EPSF) / ssum;    // 1/sigma
        g_inv_arr[0] = v; inv_s[0] = v;
    }
    __syncthreads();

    // ---- hh: W [512,128] ----
    if (tid < HID) {
        float s = 0.f;
        for (int g = 0; g < GATES; g++) s += whh[g * HID + tid] * uhh[g];
        tv[tid] = s;
    }
    __syncthreads();
    if (tid == 0) {
        float n = 0.f;
        for (int k = 0; k < HID; k++) n += tv[k] * tv[k];
        nrm = sqrtf(n) + EPSF;
    }
    __syncthreads();
    {
        float a = 0.f;
        for (int k = 0; k < HID; k++) a += whh[tid * HID + k] * tv[k];
        a /= nrm;
        red[tid] = a * a;
    }
    __syncthreads();
    for (int off = 256; off; off >>= 1) {
        if (tid < off) red[tid] += red[tid + off];
        __syncthreads();
    }
    if (tid == 0) {
        float ssum = red[0];
        float v = (sqrtf(ssum) + EPSF) / ssum;
        g_inv_arr[1] = v; inv_s[1] = v;
    }
    __syncthreads();

    // ---- fc: W [1,128] ----
    red[tid] = (tid < HID) ? wfc[tid] * wfc[tid] : 0.f;
    __syncthreads();
    for (int off = 256; off; off >>= 1) {
        if (tid < off) red[tid] += red[tid + off];
        __syncthreads();
    }
    if (tid == 0) {
        float wn2 = red[0];
        float u0  = ufc[0];
        float tn  = fabsf(u0) * sqrtf(wn2) + EPSF;   // ||W^T u||
        float s   = u0 * wn2 / tn;                   // W @ v (scalar)
        float sig = s * s / (fabsf(s) + EPSF);
        float v = 1.f / sig;
        g_inv_arr[2] = v; inv_s[2] = v;
    }
    __syncthreads();

    // ---- scale + pack ----
    float i0 = inv_s[0], i1 = inv_s[1];
    // Wih transposed & scaled: g_wt[c*512+g]
    for (int c = 0; c < CIN; c++)
        g_wt[c * GATES + tid] = wih[tid * CIN + c] * i0;
    g_bias[tid] = bih[tid] + bhh[tid];
    // Whh scaled -> fp16
    for (int k = 0; k < HID; k++)
        g_whh_h[tid * HID + k] = __float2half(whh[tid * HID + k] * i1);
}

// ---------------------------------------------------------------------------
// Kernel C: gates_x = x_aug @ Wih_n^T + bias.  M=B*T rows, K=33, N=512.
// grid = 8192 blocks x 32 rows, 256 threads (each: 2 gates x 32 rows)
// ---------------------------------------------------------------------------
__global__ void gates_kernel(const float* __restrict__ x)
{
    __shared__ float xs[32][CIN + 3];   // pad
    int row0 = blockIdx.x * 32;
    int tid  = threadIdx.x;

    for (int i = tid; i < 32 * CHAN; i += 256) {
        int r = i >> 5, c = i & 31;
        xs[r][c] = x[(size_t)(row0 + r) * CHAN + c];
    }
    if (tid < 32) xs[tid][CHAN] = g_std_arr[(row0 + tid) & (T_STEPS - 1)];
    __syncthreads();

    int g = tid;
    float b0v = g_bias[g], b1v = g_bias[g + 256];

    for (int rb = 0; rb < 32; rb += 8) {
        float a0[8], a1[8];
        #pragma unroll
        for (int r = 0; r < 8; r++) { a0[r] = b0v; a1[r] = b1v; }
        #pragma unroll
        for (int c = 0; c < CIN; c++) {
            float w0 = g_wt[c * GATES + g];
            float w1 = g_wt[c * GATES + g + 256];
            #pragma unroll
            for (int r = 0; r < 8; r++) {
                float xv = xs[rb + r][c];
                a0[r] = fmaf(xv, w0, a0[r]);
                a1[r] = fmaf(xv, w1, a1[r]);
            }
        }
        #pragma unroll
        for (int r = 0; r < 8; r++) {
            size_t o = (size_t)(row0 + rb + r) * GATES;
            g_gates[o + g]       = a0[r];
            g_gates[o + g + 256] = a1[r];
        }
    }
}

// ---------------------------------------------------------------------------
// Kernel D: persistent LSTM + online-softmax attention + FC epilogue.
// 128 blocks x 4 batch rows, 256 threads, 512 time steps.
// ---------------------------------------------------------------------------
__device__ __forceinline__ float sigmoidf_(float x) {
    return 1.f / (1.f + __expf(-x));
}

__global__ void __launch_bounds__(256, 1)
lstm_kernel(const float* __restrict__ attn_w,
            const float* __restrict__ fc_w,
            const float* __restrict__ fc_b,
            float* __restrict__ out)
{
    extern __shared__ unsigned char smem_raw[];
    __half2* whh2 = (__half2*)smem_raw;                          // [512][65] padded
    float*   h_s  = (float*)(smem_raw + GATES * 65 * 4);         // [4][128]
    float*   gts  = h_s + 4 * HID;                               // [4][512]
    float*   aw_s = gts + 4 * GATES;                             // [128]
    float*   fw_s = aw_s + HID;                                  // [128]
    float*   mrow = fw_s + HID;                                  // [4]
    float*   srow = mrow + 4;                                    // [4]
    float*   alph = srow + 4;                                    // [4]
    float*   prow = alph + 4;                                    // [4]

    int tid = threadIdx.x;
    int b0  = blockIdx.x * 4;
    int wid = tid >> 5, lane = tid & 31;

    // init smem
    const __half2* wg = (const __half2*)g_whh_h;
    for (int i = tid; i < GATES * (HID / 2); i += 256) {
        int g = i >> 6, k2 = i & 63;
        whh2[g * 65 + k2] = wg[g * 64 + k2];
    }
    for (int i = tid; i < 4 * HID; i += 256) h_s[i] = 0.f;
    if (tid < HID) { aw_s[tid] = attn_w[tid]; fw_s[tid] = fc_w[tid]; }
    if (tid < 4)   { mrow[tid] = -INFINITY; srow[tid] = 0.f; }
    __syncthreads();

    // per-thread state: gates g0=tid, g1=tid+256 (all 4 rows);
    // pointwise slots idx = tid + 256*p -> (r = idx>>7, j = idx&127)
    float cst[2]  = {0.f, 0.f};
    float acc[2]  = {0.f, 0.f};
    int   r_of[2] = { tid >> 7, (tid + 256) >> 7 };
    int   j_of[2] = { tid & 127, (tid + 256) & 127 };

    const __half2* w0 = &whh2[tid * 65];
    const __half2* w1 = &whh2[(tid + 256) * 65];
    const float2*  h2 = (const float2*)h_s;

    for (int t = 0; t < T_STEPS; t++) {
        // prefetch gates_x (latency hidden under the matvec)
        float gx0[4], gx1[4];
        #pragma unroll
        for (int r = 0; r < 4; r++) {
            size_t base = ((size_t)(b0 + r) * T_STEPS + t) * GATES;
            gx0[r] = g_gates[base + tid];
            gx1[r] = g_gates[base + tid + 256];
        }

        // gates += h @ Whh^T
        float a0[4] = {0.f, 0.f, 0.f, 0.f};
        float a1[4] = {0.f, 0.f, 0.f, 0.f};
        #pragma unroll 16
        for (int k2 = 0; k2 < 64; k2++) {
            float2 wa = __half22float2(w0[k2]);
            float2 wb = __half22float2(w1[k2]);
            #pragma unroll
            for (int r = 0; r < 4; r++) {
                float2 hv = h2[r * 64 + k2];
                a0[r] = fmaf(wa.x, hv.x, fmaf(wa.y, hv.y, a0[r]));
                a1[r] = fmaf(wb.x, hv.x, fmaf(wb.y, hv.y, a1[r]));
            }
        }
        #pragma unroll
        for (int r = 0; r < 4; r++) {
            gts[r * GATES + tid]       = a0[r] + gx0[r];
            gts[r * GATES + tid + 256] = a1[r] + gx1[r];
        }
        __syncthreads();

        // pointwise LSTM cell
        float hval[2];
        #pragma unroll
        for (int p = 0; p < 2; p++) {
            int r = r_of[p], j = j_of[p];
            const float* gr = &gts[r * GATES];
            float gi = gr[j], gf = gr[HID + j], gg = gr[2 * HID + j], go = gr[3 * HID + j];
            float iv = sigmoidf_(gi);
            float fv = sigmoidf_(gf);
            float gv = tanhf(gg);
            float ov = sigmoidf_(go);
            float c  = fv * cst[p] + iv * gv;
            cst[p]   = c;
            float hv = ov * tanhf(c);
            hval[p]  = hv;
            h_s[r * HID + j] = hv;
        }
        __syncthreads();

        // attention logit per row (attn_b dropped: softmax shift-invariant)
        if (wid < 4) {
            float l = 0.f;
            #pragma unroll
            for (int j = lane; j < HID; j += 32) l += h_s[wid * HID + j] * aw_s[j];
            #pragma unroll
            for (int off = 16; off; off >>= 1)
                l += __shfl_xor_sync(0xffffffffu, l, off);
            if (lane == 0) {
                float mold = mrow[wid];
                float mnew = fmaxf(mold, l);
                float al   = __expf(mold - mnew);     // 0 on first step
                float pv   = __expf(l - mnew);
                mrow[wid]  = mnew;
                srow[wid]  = srow[wid] * al + pv;
                alph[wid]  = al;
                prow[wid]  = pv;
            }
        }
        __syncthreads();

        // online accumulate pooled vector
        #pragma unroll
        for (int p = 0; p < 2; p++) {
            int r = r_of[p];
            acc[p] = acc[p] * alph[r] + prow[r] * hval[p];
        }
        // (next gate-accum reads h_s written before last sync; gts rewritten
        //  only after next iteration's sync1 -> safe)
        __syncthreads();
    }

    // epilogue: pooled = acc/s ; score = pooled . (fc_w/sigma) + fc_b
    #pragma unroll
    for (int p = 0; p < 2; p++) {
        int r = r_of[p], j = j_of[p];
        gts[r * HID + j] = acc[p] / srow[r];
    }
    __syncthreads();
    if (wid < 4) {
        float sc = 0.f;
        #pragma unroll
        for (int j = lane; j < HID; j += 32) sc += gts[wid * HID + j] * fw_s[j];
        #pragma unroll
        for (int off = 16; off; off >>= 1)
            sc += __shfl_xor_sync(0xffffffffu, sc, off);
        if (lane == 0)
            out[b0 + wid] = sc * g_inv_arr[2] + fc_b[0];
    }
}

// ---------------------------------------------------------------------------
extern "C" void kernel_launch(void* const* d_in, const int* in_sizes, int n_in,
                              void* d_out, int out_size)
{
    const float* x      = (const float*)d_in[0];
    const float* w_ih   = (const float*)d_in[1];
    const float* u_ih   = (const float*)d_in[2];
    const float* w_hh   = (const float*)d_in[3];
    const float* u_hh   = (const float*)d_in[4];
    const float* b_ih   = (const float*)d_in[5];
    const float* b_hh   = (const float*)d_in[6];
    const float* attn_w = (const float*)d_in[7];
    // d_in[8] = attn_b (softmax shift-invariant, unused)
    const float* fc_w   = (const float*)d_in[9];
    const float* u_fc   = (const float*)d_in[10];
    const float* fc_b   = (const float*)d_in[11];
    float* out = (float*)d_out;

    std_kernel<<<T_STEPS, 256>>>(x);
    prep_kernel<<<1, 512>>>(w_ih, u_ih, w_hh, u_hh, b_ih, b_hh, fc_w, u_fc);
    gates_kernel<<<(BATCH * T_STEPS) / 32, 256>>>(x);

    int smem = GATES * 65 * 4            // whh2 padded
             + 4 * HID * 4               // h_s
             + 4 * GATES * 4             // gts
             + 2 * HID * 4               // aw_s, fw_s
             + 16 * 4;                   // scalars
    cudaFuncSetAttribute(lstm_kernel, cudaFuncAttributeMaxDynamicSharedMemorySize, smem);
    lstm_kernel<<<BATCH / 4, 256, smem>>>(attn_w, fc_w, fc_b, out);
}

// round 7
// speedup vs baseline: 1.0469x; 1.0469x over previous
#include <cuda_runtime.h>
#include <cuda_bf16.h>
#include <math.h>

#define BATCH   512
#define T_STEPS 512
#define CHAN    32
#define CIN     33
#define HID     128
#define GATES   512   // 4*H
#define EPSF    1e-12f

typedef unsigned long long ull_t;

// ---------------------------------------------------------------------------
// f32x2 packed-math helpers (Blackwell FFMA2 path — only reachable via PTX)
// ---------------------------------------------------------------------------
__device__ __forceinline__ void ffma2(ull_t& d, ull_t a, ull_t b) {
    asm("fma.rn.f32x2 %0, %1, %2, %0;" : "+l"(d) : "l"(a), "l"(b));
}
// (bf16_lo, bf16_hi) packed in u32 -> (f32_lo, f32_hi) packed b64 (pure ALU)
__device__ __forceinline__ ull_t bf2_to_f32x2(unsigned int u) {
    ull_t r;
    asm("{\n\t.reg .b32 lo, hi;\n\t"
        "shl.b32 lo, %1, 16;\n\t"
        "and.b32 hi, %1, 0xFFFF0000;\n\t"
        "mov.b64 %0, {lo, hi};\n\t}" : "=l"(r) : "r"(u));
    return r;
}
__device__ __forceinline__ ull_t pack_dup(float v) {
    ull_t r; unsigned int b = __float_as_uint(v);
    asm("mov.b64 %0, {%1, %1};" : "=l"(r) : "r"(b));
    return r;
}
__device__ __forceinline__ float2 unpack2(ull_t d) {
    unsigned int lo, hi;
    asm("mov.b64 {%0, %1}, %2;" : "=r"(lo), "=r"(hi) : "l"(d));
    return make_float2(__uint_as_float(lo), __uint_as_float(hi));
}
__device__ __forceinline__ float hsum2(ull_t d) {
    float2 f = unpack2(d); return f.x + f.y;
}

// ---------------------------------------------------------------------------
// Device scratch (static; allocations are forbidden)
// ---------------------------------------------------------------------------
__device__ float        g_std_arr[T_STEPS];             // minibatch-std scalar per t
__device__ float        g_inv_arr[4];                   // 1/sigma: ih, hh, fc
__device__ float        g_wt[CIN * GATES];              // Wih^T scaled: [33][512]
__device__ float        g_bias[GATES];                  // b_ih + b_hh
__device__ unsigned int g_whh_p[(HID / 2) * GATES];     // bf16 k-pairs, k2-major [64][512]
__device__ float        g_gates[(size_t)BATCH * T_STEPS * GATES]; // 536 MB gates_x

// ---------------------------------------------------------------------------
// Kernel A: minibatch std feature. grid=T, block=256 (8 b-seg x 32 chan)
// ---------------------------------------------------------------------------
__global__ void std_kernel(const float* __restrict__ x)
{
    int t   = blockIdx.x;
    int tid = threadIdx.x;
    int c   = tid & 31;
    int seg = tid >> 5;

    float s = 0.f, ss = 0.f;
    for (int b = seg; b < BATCH; b += 8) {
        float v = x[((size_t)b * T_STEPS + t) * CHAN + c];
        s  += v;
        ss += v * v;
    }
    __shared__ float sm1[256], sm2[256];
    sm1[tid] = s; sm2[tid] = ss;
    __syncthreads();
    if (seg == 0) {
        for (int k = 1; k < 8; k++) { s += sm1[k * 32 + c]; ss += sm2[k * 32 + c]; }
        float mean = s * (1.f / 512.f);
        float var  = (ss - 512.f * mean * mean) * (1.f / 511.f);
        float sd   = sqrtf(fmaxf(var, 0.f));
        #pragma unroll
        for (int off = 16; off; off >>= 1)
            sd += __shfl_xor_sync(0xffffffffu, sd, off);
        if (c == 0) g_std_arr[t] = sd * (1.f / 32.f);
    }
}

// ---------------------------------------------------------------------------
// Kernel B: spectral norms (one power iteration, matching reference exactly)
// then scale+transpose Wih, combine bias, quantize Whh to bf16 k-pairs.
// single block, 512 threads
// ---------------------------------------------------------------------------
__global__ void prep_kernel(const float* __restrict__ wih, const float* __restrict__ uih,
                            const float* __restrict__ whh, const float* __restrict__ uhh,
                            const float* __restrict__ bih, const float* __restrict__ bhh,
                            const float* __restrict__ wfc, const float* __restrict__ ufc)
{
    __shared__ float tv[HID];
    __shared__ float red[512];
    __shared__ float nrm;
    __shared__ float inv_s[4];
    int tid = threadIdx.x;

    // ---- ih: W [512,33] ----
    if (tid < CIN) {
        float s = 0.f;
        for (int g = 0; g < GATES; g++) s += wih[g * CIN + tid] * uih[g];
        tv[tid] = s;
    }
    __syncthreads();
    if (tid == 0) {
        float n = 0.f;
        for (int c = 0; c < CIN; c++) n += tv[c] * tv[c];
        nrm = sqrtf(n) + EPSF;
    }
    __syncthreads();
    {
        float a = 0.f;
        for (int c = 0; c < CIN; c++) a += wih[tid * CIN + c] * tv[c];
        a /= nrm;
        red[tid] = a * a;
    }
    __syncthreads();
    for (int off = 256; off; off >>= 1) {
        if (tid < off) red[tid] += red[tid + off];
        __syncthreads();
    }
    if (tid == 0) {
        float ssum = red[0];                      // ||W v||^2
        float v = (sqrtf(ssum) + EPSF) / ssum;    // 1/sigma
        g_inv_arr[0] = v; inv_s[0] = v;
    }
    __syncthreads();

    // ---- hh: W [512,128] ----
    if (tid < HID) {
        float s = 0.f;
        for (int g = 0; g < GATES; g++) s += whh[g * HID + tid] * uhh[g];
        tv[tid] = s;
    }
    __syncthreads();
    if (tid == 0) {
        float n = 0.f;
        for (int k = 0; k < HID; k++) n += tv[k] * tv[k];
        nrm = sqrtf(n) + EPSF;
    }
    __syncthreads();
    {
        float a = 0.f;
        for (int k = 0; k < HID; k++) a += whh[tid * HID + k] * tv[k];
        a /= nrm;
        red[tid] = a * a;
    }
    __syncthreads();
    for (int off = 256; off; off >>= 1) {
        if (tid < off) red[tid] += red[tid + off];
        __syncthreads();
    }
    if (tid == 0) {
        float ssum = red[0];
        float v = (sqrtf(ssum) + EPSF) / ssum;
        g_inv_arr[1] = v; inv_s[1] = v;
    }
    __syncthreads();

    // ---- fc: W [1,128] ----
    red[tid] = (tid < HID) ? wfc[tid] * wfc[tid] : 0.f;
    __syncthreads();
    for (int off = 256; off; off >>= 1) {
        if (tid < off) red[tid] += red[tid + off];
        __syncthreads();
    }
    if (tid == 0) {
        float wn2 = red[0];
        float u0  = ufc[0];
        float tn  = fabsf(u0) * sqrtf(wn2) + EPSF;   // ||W^T u||
        float s   = u0 * wn2 / tn;                   // W @ v (scalar)
        float sig = s * s / (fabsf(s) + EPSF);
        float v = 1.f / sig;
        g_inv_arr[2] = v; inv_s[2] = v;
    }
    __syncthreads();

    // ---- scale + pack ----
    float i0 = inv_s[0], i1 = inv_s[1];
    // Wih transposed & scaled: g_wt[c*512+g]
    for (int c = 0; c < CIN; c++)
        g_wt[c * GATES + tid] = wih[tid * CIN + c] * i0;
    g_bias[tid] = bih[tid] + bhh[tid];
    // Whh scaled -> bf16 k-pairs, k2-major: g_whh_p[k2*512 + g]
    for (int k2 = 0; k2 < HID / 2; k2++) {
        float we = whh[tid * HID + 2 * k2]     * i1;
        float wo = whh[tid * HID + 2 * k2 + 1] * i1;
        unsigned int be = (unsigned int)__bfloat16_as_ushort(__float2bfloat16(we));
        unsigned int bo = (unsigned int)__bfloat16_as_ushort(__float2bfloat16(wo));
        g_whh_p[k2 * GATES + tid] = be | (bo << 16);
    }
}

// ---------------------------------------------------------------------------
// Kernel C: gates_x = x_aug @ Wih_n^T + bias (f32x2 packed over gate pairs).
// grid = 8192 blocks x 32 rows, 256 threads; thread t owns gates (2t, 2t+1).
// ---------------------------------------------------------------------------
__global__ void gates_kernel(const float* __restrict__ x)
{
    __shared__ ull_t xs_d[CIN * 34];   // x duplicated (v,v), [c][34 rows]
    int row0 = blockIdx.x * 32;
    int tid  = threadIdx.x;

    for (int i = tid; i < 32 * CHAN; i += 256) {
        int r = i >> 5, c = i & 31;
        xs_d[c * 34 + r] = pack_dup(x[(size_t)(row0 + r) * CHAN + c]);
    }
    if (tid < 32)
        xs_d[CHAN * 34 + tid] = pack_dup(g_std_arr[(row0 + tid) & (T_STEPS - 1)]);
    __syncthreads();

    const ull_t* wt2   = (const ull_t*)g_wt;     // (w_2t, w_2t+1) f32 pairs
    const ull_t* bias2 = (const ull_t*)g_bias;
    ull_t*       gout  = (ull_t*)g_gates;
    ull_t bp = bias2[tid];

    for (int rb = 0; rb < 32; rb += 8) {
        ull_t acc[8];
        #pragma unroll
        for (int r = 0; r < 8; r++) acc[r] = bp;
        #pragma unroll
        for (int c = 0; c < CIN; c++) {
            ull_t w = wt2[c * (GATES / 2) + tid];
            #pragma unroll
            for (int r = 0; r < 8; r++)
                ffma2(acc[r], w, xs_d[c * 34 + rb + r]);
        }
        #pragma unroll
        for (int r = 0; r < 8; r++)
            gout[(size_t)(row0 + rb + r) * (GATES / 2) + tid] = acc[r];
    }
}

// ---------------------------------------------------------------------------
// Kernel D: persistent LSTM + online-softmax attention + FC epilogue.
// 128 blocks x 4 batch rows, 256 threads, 512 steps.
// Thread t owns gates (2t, 2t+1); matvec packed over k (even k in lo lane).
// ---------------------------------------------------------------------------
__device__ __forceinline__ float sigmoidf_(float x) {
    return 1.f / (1.f + __expf(-x));
}

__global__ void __launch_bounds__(256, 1)
lstm_kernel(const float* __restrict__ attn_w,
            const float* __restrict__ fc_w,
            const float* __restrict__ fc_b,
            float* __restrict__ out)
{
    extern __shared__ unsigned char smem_raw[];
    unsigned int* wsm = (unsigned int*)smem_raw;                 // [64 k2][512 g] bf16-pairs
    float* h_s  = (float*)(smem_raw + (HID / 2) * GATES * 4);    // [4][128]
    float* gts  = h_s + 4 * HID;                                 // [4][512]
    float* aw_s = gts + 4 * GATES;                               // [128]
    float* fw_s = aw_s + HID;                                    // [128]
    float* mrow = fw_s + HID;                                    // [4]
    float* srow = mrow + 4;                                      // [4]
    float* alph = srow + 4;                                      // [4]
    float* prow = alph + 4;                                      // [4]

    int tid = threadIdx.x;
    int b0  = blockIdx.x * 4;
    int wid = tid >> 5, lane = tid & 31;

    // init smem
    for (int i = tid; i < (HID / 2) * GATES; i += 256) wsm[i] = g_whh_p[i];
    for (int i = tid; i < 4 * HID; i += 256) h_s[i] = 0.f;
    if (tid < HID) { aw_s[tid] = attn_w[tid]; fw_s[tid] = fc_w[tid]; }
    if (tid < 4)   { mrow[tid] = -INFINITY; srow[tid] = 0.f; }
    __syncthreads();

    // pointwise slots: idx = tid + 256*p -> (r = idx>>7, j = idx&127)
    float cst[2]  = {0.f, 0.f};
    float acc[2]  = {0.f, 0.f};
    int   r_of[2] = { tid >> 7, (tid + 256) >> 7 };
    int   j_of[2] = { tid & 127, (tid + 256) & 127 };

    const ull_t* wp = (const ull_t*)wsm;          // [64][256] ull: (g=2t, g=2t+1)
    const ull_t* h8 = (const ull_t*)h_s;          // (h[2k2], h[2k2+1]) pairs
    const ull_t* gsrc = (const ull_t*)g_gates;
    ull_t* gts2 = (ull_t*)gts;

    for (int t = 0; t < T_STEPS; t++) {
        // prefetch gates_x pairs (latency hidden under the matvec)
        ull_t gx[4];
        #pragma unroll
        for (int r = 0; r < 4; r++)
            gx[r] = gsrc[((size_t)(b0 + r) * T_STEPS + t) * (GATES / 2) + tid];

        // gates += h @ Whh^T  (packed over k: acc = (sum_even_k, sum_odd_k))
        ull_t a0[4] = {0, 0, 0, 0};   // gate 2t
        ull_t a1[4] = {0, 0, 0, 0};   // gate 2t+1
        #pragma unroll 16
        for (int k2 = 0; k2 < HID / 2; k2++) {
            ull_t wpair = wp[k2 * (GATES / 2) + tid];   // LDS.64, conflict-free
            float2 wb = unpack2(wpair);
            ull_t w0 = bf2_to_f32x2(__float_as_uint(wb.x));
            ull_t w1 = bf2_to_f32x2(__float_as_uint(wb.y));
            #pragma unroll
            for (int r = 0; r < 4; r++) {
                ull_t hv = h8[r * (HID / 2) + k2];      // LDS.64 broadcast
                ffma2(a0[r], w0, hv);
                ffma2(a1[r], w1, hv);
            }
        }
        #pragma unroll
        for (int r = 0; r < 4; r++) {
            float2 gxf = unpack2(gx[r]);
            float g0 = hsum2(a0[r]) + gxf.x;
            float g1 = hsum2(a1[r]) + gxf.y;
            ull_t pr;
            asm("mov.b64 %0, {%1, %2};" : "=l"(pr)
                : "r"(__float_as_uint(g0)), "r"(__float_as_uint(g1)));
            gts2[r * (GATES / 2) + tid] = pr;           // STS.64
        }
        __syncthreads();

        // pointwise LSTM cell
        float hval[2];
        #pragma unroll
        for (int p = 0; p < 2; p++) {
            int r = r_of[p], j = j_of[p];
            const float* gr = &gts[r * GATES];
            float gi = gr[j], gf = gr[HID + j], gg = gr[2 * HID + j], go = gr[3 * HID + j];
            float iv = sigmoidf_(gi);
            float fv = sigmoidf_(gf);
            float gv = tanhf(gg);
            float ov = sigmoidf_(go);
            float c  = fv * cst[p] + iv * gv;
            cst[p]   = c;
            float hv = ov * tanhf(c);
            hval[p]  = hv;
            h_s[r * HID + j] = hv;
        }
        __syncthreads();

        // attention logit per row (attn_b dropped: softmax shift-invariant)
        if (wid < 4) {
            float l = 0.f;
            #pragma unroll
            for (int j = lane; j < HID; j += 32) l += h_s[wid * HID + j] * aw_s[j];
            #pragma unroll
            for (int off = 16; off; off >>= 1)
                l += __shfl_xor_sync(0xffffffffu, l, off);
            if (lane == 0) {
                float mold = mrow[wid];
                float mnew = fmaxf(mold, l);
                float al   = __expf(mold - mnew);
                float pv   = __expf(l - mnew);
                mrow[wid]  = mnew;
                srow[wid]  = srow[wid] * al + pv;
                alph[wid]  = al;
                prow[wid]  = pv;
            }
        }
        __syncthreads();

        // online accumulate pooled vector
        #pragma unroll
        for (int p = 0; p < 2; p++) {
            int r = r_of[p];
            acc[p] = acc[p] * alph[r] + prow[r] * hval[p];
        }
        __syncthreads();
    }

    // epilogue: pooled = acc/s ; score = pooled . (fc_w/sigma) + fc_b
    #pragma unroll
    for (int p = 0; p < 2; p++) {
        int r = r_of[p], j = j_of[p];
        gts[r * HID + j] = acc[p] / srow[r];
    }
    __syncthreads();
    if (wid < 4) {
        float sc = 0.f;
        #pragma unroll
        for (int j = lane; j < HID; j += 32) sc += gts[wid * HID + j] * fw_s[j];
        #pragma unroll
        for (int off = 16; off; off >>= 1)
            sc += __shfl_xor_sync(0xffffffffu, sc, off);
        if (lane == 0)
            out[b0 + wid] = sc * g_inv_arr[2] + fc_b[0];
    }
}

// ---------------------------------------------------------------------------
extern "C" void kernel_launch(void* const* d_in, const int* in_sizes, int n_in,
                              void* d_out, int out_size)
{
    const float* x      = (const float*)d_in[0];
    const float* w_ih   = (const float*)d_in[1];
    const float* u_ih   = (const float*)d_in[2];
    const float* w_hh   = (const float*)d_in[3];
    const float* u_hh   = (const float*)d_in[4];
    const float* b_ih   = (const float*)d_in[5];
    const float* b_hh   = (const float*)d_in[6];
    const float* attn_w = (const float*)d_in[7];
    // d_in[8] = attn_b (softmax shift-invariant, unused)
    const float* fc_w   = (const float*)d_in[9];
    const float* u_fc   = (const float*)d_in[10];
    const float* fc_b   = (const float*)d_in[11];
    float* out = (float*)d_out;

    std_kernel<<<T_STEPS, 256>>>(x);
    prep_kernel<<<1, 512>>>(w_ih, u_ih, w_hh, u_hh, b_ih, b_hh, fc_w, u_fc);
    gates_kernel<<<(BATCH * T_STEPS) / 32, 256>>>(x);

    int smem = (HID / 2) * GATES * 4      // bf16-pair weights: 128 KB
             + 4 * HID * 4                // h_s
             + 4 * GATES * 4              // gts
             + 2 * HID * 4                // aw_s, fw_s
             + 16 * 4;                    // scalars
    cudaFuncSetAttribute(lstm_kernel, cudaFuncAttributeMaxDynamicSharedMemorySize, smem);
    lstm_kernel<<<BATCH / 4, 256, smem>>>(attn_w, fc_w, fc_b, out);
}